// round 8
// baseline (speedup 1.0000x reference)
#include <cuda_runtime.h>
#include <cstdint>

// LDDMM variational shooting RHS, Gaussian kernel sigma=0.1, B=1, N=8192, D=3.
//
// dcp_i  = sum_j exp(-50*|xi-xj|^2) * p_j                    (p = clamp(mom,-1,1))
// dmom_i = 100 * sum_j K_ij (p_i.p_j) (x_i - x_j)
//
// O(N^2) pairwise on the FMA pipe with fma.rn.f32x2 (2 j-points per instr).
// exp(-50 d2) = 2^(-d2') with coordinates pre-scaled by s = sqrt(50*log2 e);
// magic-number range reduction + deg-4 economized polynomial (no MUFU).
// Exponent scale built per-lane as max(0x3F800000 - (n<<23), 0) via a single
// IMAD+IMNMX pair (the integer max IS the underflow clamp). Shared j-tiles are
// stored pre-packed (ulonglong2) so no pack movs are needed in the hot loop.
// j-range split across blockIdx.y into deterministic partials ([g][d][i],
// coalesced), reduced by a second kernel (8-way MLP, fixed-order -> determ.).

#define THREADS 128
#define IPT     2                 // i-points per thread
#define ISPAN   (THREADS * IPT)   // 256 i per block
#define JTILE   256               // j per block (1024 blocks -> good wave balance)
#define JT2     (JTILE / 2)       // packed pairs in tile
#define MAXN    16384
#define MAXG    ((MAXN + JTILE - 1) / JTILE)

// coordinate prescale: s^2 = 50*log2(e) = 72.13475204
#define SSCALE  8.4932180f
#define MAGIC   12582912.0f        // 1.5 * 2^23

// partials: g_part[g][d*MAXN + i], d=0..2 dcp, d=3..5 sum w*(xj-xi) (scaled)
__device__ __align__(16) float g_part[MAXG][6 * MAXN];

using u64 = unsigned long long;

__device__ __forceinline__ u64 pk2(float a, float b) {
    u64 r; asm("mov.b64 %0, {%1, %2};" : "=l"(r) : "f"(a), "f"(b)); return r;
}
__device__ __forceinline__ void upk2(u64 v, float& a, float& b) {
    asm("mov.b64 {%0, %1}, %2;" : "=f"(a), "=f"(b) : "l"(v));
}
__device__ __forceinline__ u64 f2add(u64 a, u64 b) {
    u64 r; asm("add.rn.f32x2 %0, %1, %2;" : "=l"(r) : "l"(a), "l"(b)); return r;
}
__device__ __forceinline__ u64 f2mul(u64 a, u64 b) {
    u64 r; asm("mul.rn.f32x2 %0, %1, %2;" : "=l"(r) : "l"(a), "l"(b)); return r;
}
__device__ __forceinline__ u64 f2fma(u64 a, u64 b, u64 c) {
    u64 r; asm("fma.rn.f32x2 %0, %1, %2, %3;" : "=l"(r) : "l"(a), "l"(b), "l"(c)); return r;
}

__device__ __forceinline__ float clamp1(float v) {
    return fminf(fmaxf(v, -1.0f), 1.0f);
}

__global__ __launch_bounds__(THREADS)
void lddmm_main(const float* __restrict__ mom, const float* __restrict__ x, int N)
{
    // pre-packed j tiles: each entry = two u64 f32x2 lanes
    __shared__ ulonglong2 sT0[JT2];  // (xj, yj)   scaled coords, packed (j0,j1)
    __shared__ ulonglong2 sT1[JT2];  // (zj, px)
    __shared__ ulonglong2 sT2[JT2];  // (py, pz)

    const int t  = threadIdx.x;
    const int bi = blockIdx.x;
    const int g  = blockIdx.y;
    const int jbase = g * JTILE;

    // ---- load j tile (padding: x=0 (scale->0), p=0 -> zero contribution) ----
    for (int k = t; k < JT2; k += THREADS) {
        int j0 = jbase + 2 * k, j1 = j0 + 1;
        float X0 = 0.f, Y0 = 0.f, Z0 = 0.f, P0 = 0.f, Q0 = 0.f, R0 = 0.f;
        float X1 = 0.f, Y1 = 0.f, Z1 = 0.f, P1 = 0.f, Q1 = 0.f, R1 = 0.f;
        if (j0 < N) {
            X0 = x[3 * j0] * SSCALE; Y0 = x[3 * j0 + 1] * SSCALE; Z0 = x[3 * j0 + 2] * SSCALE;
            P0 = clamp1(mom[3 * j0]); Q0 = clamp1(mom[3 * j0 + 1]); R0 = clamp1(mom[3 * j0 + 2]);
        }
        if (j1 < N) {
            X1 = x[3 * j1] * SSCALE; Y1 = x[3 * j1 + 1] * SSCALE; Z1 = x[3 * j1 + 2] * SSCALE;
            P1 = clamp1(mom[3 * j1]); Q1 = clamp1(mom[3 * j1 + 1]); R1 = clamp1(mom[3 * j1 + 2]);
        }
        ulonglong2 v;
        v.x = pk2(X0, X1); v.y = pk2(Y0, Y1); sT0[k] = v;
        v.x = pk2(Z0, Z1); v.y = pk2(P0, P1); sT1[k] = v;
        v.x = pk2(Q0, Q1); v.y = pk2(R0, R1); sT2[k] = v;
    }
    __syncthreads();

    // ---- per-thread i registers (broadcast packed); split-stride i for coalesced stores ----
    u64 nxi[IPT], nyi[IPT], nzi[IPT];   // packed (-xi_s, -xi_s)
    u64 pxi[IPT], pyi[IPT], pzi[IPT];   // packed (pi, pi)
    u64 adx[IPT], ady[IPT], adz[IPT];   // sum w*(xj_s - xi_s)
    u64 acx[IPT], acy[IPT], acz[IPT];   // sum e*pj

    const int i0 = bi * ISPAN + t;
#pragma unroll
    for (int ii = 0; ii < IPT; ii++) {
        int i = i0 + ii * THREADS;
        float X = 0.f, Y = 0.f, Z = 0.f, P = 0.f, Q = 0.f, R = 0.f;
        if (i < N) {
            X = x[3 * i] * SSCALE; Y = x[3 * i + 1] * SSCALE; Z = x[3 * i + 2] * SSCALE;
            P = clamp1(mom[3 * i]); Q = clamp1(mom[3 * i + 1]); R = clamp1(mom[3 * i + 2]);
        }
        nxi[ii] = pk2(-X, -X); nyi[ii] = pk2(-Y, -Y); nzi[ii] = pk2(-Z, -Z);
        pxi[ii] = pk2(P, P);   pyi[ii] = pk2(Q, Q);   pzi[ii] = pk2(R, R);
        adx[ii] = 0ull; ady[ii] = 0ull; adz[ii] = 0ull;
        acx[ii] = 0ull; acy[ii] = 0ull; acz[ii] = 0ull;
    }

    // packed constants
    const u64 MAG2  = pk2(MAGIC, MAGIC);
    const u64 NMAG2 = pk2(-MAGIC, -MAGIC);
    const u64 NONE2 = pk2(-1.0f, -1.0f);
    const u64 ONE2  = pk2(1.0f, 1.0f);
    // 2^(-f) on f in [-0.5,0.5]: deg-4, Chebyshev-economized, max err ~5e-6
    const u64 C4_2  = pk2( 0.00961813f,  0.00961813f);
    const u64 NC3_2 = pk2(-0.05592078f, -0.05592078f);
    const u64 C2_2  = pk2( 0.24022651f,  0.24022651f);
    const u64 NC1_2 = pk2(-0.69312114f, -0.69312114f);

    // ---- main pairwise loop: each iter = 2 j-points x IPT i-points ----
#pragma unroll 2
    for (int k = 0; k < JT2; k++) {
        ulonglong2 t0 = sT0[k], t1 = sT1[k], t2 = sT2[k];
        u64 xj = t0.x, yj = t0.y, zj = t1.x;
        u64 qx = t1.y, qy = t2.x, qz = t2.y;
#pragma unroll
        for (int ii = 0; ii < IPT; ii++) {
            u64 dx = f2add(xj, nxi[ii]);            // scaled deltas
            u64 dy = f2add(yj, nyi[ii]);
            u64 dz = f2add(zj, nzi[ii]);
            u64 d2 = f2mul(dx, dx);
            d2 = f2fma(dy, dy, d2);
            d2 = f2fma(dz, dz, d2);                 // d2' = 72.1347*|dx|^2, in [0, ~216]
            u64 fz = f2add(d2, MAG2);               // magic round: low bits hold n+0x400000
            u64 nn = f2add(fz, NMAG2);              // n = rint(d2') as float
            u64 ff = f2fma(nn, NONE2, d2);          // f = d2' - n in [-0.5, 0.5]
            u64 p  = f2fma(C4_2, ff, NC3_2);        // 2^(-f)
            p = f2fma(p, ff, C2_2);
            p = f2fma(p, ff, NC1_2);
            p = f2fma(p, ff, ONE2);
            // scale = 2^(-n): bits = max(0x3F800000 - (n<<23), 0); the integer
            // max IS the underflow clamp (n>=127 -> 0 -> e=0 exactly).
            float fz0, fz1; upk2(fz, fz0, fz1);
            int s0i = ::max((int)(__float_as_uint(fz0) * 0xFF800000u + 0x3F800000u), 0);
            int s1i = ::max((int)(__float_as_uint(fz1) * 0xFF800000u + 0x3F800000u), 0);
            u64 s2 = pk2(__int_as_float(s0i), __int_as_float(s1i));
            u64 e = f2mul(p, s2);                   // K_ij = 2^(-d2')

            u64 pp = f2mul(pxi[ii], qx);
            pp = f2fma(pyi[ii], qy, pp);
            pp = f2fma(pzi[ii], qz, pp);            // p_i . p_j
            u64 w = f2mul(e, pp);                   // W_ij

            acx[ii] = f2fma(e, qx, acx[ii]);
            acy[ii] = f2fma(e, qy, acy[ii]);
            acz[ii] = f2fma(e, qz, acz[ii]);
            adx[ii] = f2fma(w, dx, adx[ii]);
            ady[ii] = f2fma(w, dy, ady[ii]);
            adz[ii] = f2fma(w, dz, adz[ii]);
        }
    }

    // ---- write partials, coalesced [g][d][i] layout (one writer per slot) ----
#pragma unroll
    for (int ii = 0; ii < IPT; ii++) {
        int i = i0 + ii * THREADS;
        if (i < N) {
            float u, v;
            float* P = g_part[g];
            upk2(acx[ii], u, v); P[0 * MAXN + i] = u + v;
            upk2(acy[ii], u, v); P[1 * MAXN + i] = u + v;
            upk2(acz[ii], u, v); P[2 * MAXN + i] = u + v;
            upk2(adx[ii], u, v); P[3 * MAXN + i] = u + v;
            upk2(ady[ii], u, v); P[4 * MAXN + i] = u + v;
            upk2(adz[ii], u, v); P[5 * MAXN + i] = u + v;
        }
    }
}

__global__ void lddmm_reduce(float* __restrict__ out, int N, int G)
{
    // dmom = 100 * sum w*(xi-xj) = -(100/s) * adx_sum  (coords pre-scaled by s)
    const float DSC = -100.0f / SSCALE;
    const int idx = blockIdx.x * blockDim.x + threadIdx.x;  // over 6*N scalars
    if (idx >= 6 * N) return;
    const int d = idx / N, i = idx - d * N;
    const float* col = &g_part[0][0] + d * MAXN + i;
    const long long S = 6LL * MAXN;

    float a0 = 0.f, a1 = 0.f, a2 = 0.f, a3 = 0.f;
    float a4 = 0.f, a5 = 0.f, a6 = 0.f, a7 = 0.f;
    int g = 0;
    for (; g + 8 <= G; g += 8) {        // 8 independent chains -> MLP=8
        a0 += col[(g + 0) * S]; a1 += col[(g + 1) * S];
        a2 += col[(g + 2) * S]; a3 += col[(g + 3) * S];
        a4 += col[(g + 4) * S]; a5 += col[(g + 5) * S];
        a6 += col[(g + 6) * S]; a7 += col[(g + 7) * S];
    }
    for (; g < G; g++) a0 += col[g * S];
    float s = ((a0 + a1) + (a2 + a3)) + ((a4 + a5) + (a6 + a7));

    if (d < 3) out[3 * N + i * 3 + d] = s;          // dcp
    else       out[i * 3 + (d - 3)]   = s * DSC;    // dmom
}

extern "C" void kernel_launch(void* const* d_in, const int* in_sizes, int n_in,
                              void* d_out, int out_size)
{
    const float* mom = (const float*)d_in[0];
    const float* x   = (const float*)d_in[1];
    int N = in_sizes[0] / 3;
    if (N <= 0) return;
    if (N > MAXN) N = MAXN;  // scratch bound (problem uses N=8192)

    int G   = (N + JTILE - 1) / JTILE;
    int NBI = (N + ISPAN - 1) / ISPAN;
    dim3 grid(NBI, G);
    lddmm_main<<<grid, THREADS>>>(mom, x, N);

    int tot = 6 * N;
    lddmm_reduce<<<(tot + 255) / 256, 256>>>((float*)d_out, N, G);
}

// round 9
// speedup vs baseline: 1.0152x; 1.0152x over previous
#include <cuda_runtime.h>
#include <cstdint>

// LDDMM variational shooting RHS, Gaussian kernel sigma=0.1, B=1, N=8192, D=3.
//
// dcp_i  = sum_j exp(-50*|xi-xj|^2) * p_j                    (p = clamp(mom,-1,1))
// dmom_i = 100 * ( x_i * sum_j W_ij  -  sum_j W_ij x_j ),  W_ij = K_ij (p_i.p_j)
//
// O(N^2) pairwise, fma.rn.f32x2 (2 j per instr). FMA-pipe-bound, so the hot
// loop is trimmed to 22 f32x2 ops per (2j x 1i):
//   - d2 via |xi|^2+|xj|^2-2 xi.xj (sq_j precomputed in the tile) -> no deltas
//   - accumulate {e*p_j, w*x_j, w}; x_i*SumW - Sum(w x_j) folded in at the end
//   - exp(-50 d2) = 2^(-d2') (coords pre-scaled by s=sqrt(50 log2 e)), magic
//     round + deg-3 economized poly (err ~1e-4); exponent scale is ALU-only:
//     s_bits = 0x3F800000 - (min(bits(fz),0x4B40007F)<<23)  (min = underflow clamp)
// Cross-g reduction is FUSED: last block per i-column (atomic counter) sums the
// per-g partials in fixed order (deterministic) and writes the output.

#define THREADS 128
#define IPT     2                 // i-points per thread
#define ISPAN   (THREADS * IPT)   // 256 i per block
#define JTILE   256               // j per block
#define JT2     (JTILE / 2)       // packed j-pairs in tile
#define MAXN    16384
#define MAXG    ((MAXN + JTILE - 1) / JTILE)
#define MAXBI   (MAXN / ISPAN)

// coordinate prescale: s^2 = 50*log2(e) = 72.13475204
#define SSCALE  8.4932180f
#define MAGIC   12582912.0f        // 1.5 * 2^23

// partials: g_part[g][d*MAXN + i]; d=0..2: sum e*p_j ; d=3..5: sum w*x_j ; d=6: sum w
__device__ __align__(16) float g_part[MAXG][7 * MAXN];
__device__ int g_cnt[MAXBI];       // zero-init; self-resetting per launch

using u64 = unsigned long long;

__device__ __forceinline__ u64 pk2(float a, float b) {
    u64 r; asm("mov.b64 %0, {%1, %2};" : "=l"(r) : "f"(a), "f"(b)); return r;
}
__device__ __forceinline__ void upk2(u64 v, float& a, float& b) {
    asm("mov.b64 {%0, %1}, %2;" : "=f"(a), "=f"(b) : "l"(v));
}
__device__ __forceinline__ u64 f2add(u64 a, u64 b) {
    u64 r; asm("add.rn.f32x2 %0, %1, %2;" : "=l"(r) : "l"(a), "l"(b)); return r;
}
__device__ __forceinline__ u64 f2mul(u64 a, u64 b) {
    u64 r; asm("mul.rn.f32x2 %0, %1, %2;" : "=l"(r) : "l"(a), "l"(b)); return r;
}
__device__ __forceinline__ u64 f2fma(u64 a, u64 b, u64 c) {
    u64 r; asm("fma.rn.f32x2 %0, %1, %2, %3;" : "=l"(r) : "l"(a), "l"(b), "l"(c)); return r;
}

__device__ __forceinline__ float clamp1(float v) {
    return fminf(fmaxf(v, -1.0f), 1.0f);
}

__global__ __launch_bounds__(THREADS)
void lddmm_main(const float* __restrict__ mom, const float* __restrict__ x,
                float* __restrict__ out, int N)
{
    __shared__ ulonglong2 sT0[JT2];  // (xj, yj)  scaled, packed (j0,j1)
    __shared__ ulonglong2 sT1[JT2];  // (zj, sqj) sqj = |xj_s|^2
    __shared__ ulonglong2 sT2[JT2];  // (qx, qy)  clamped momenta
    __shared__ u64        sQz[JT2];  // qz
    __shared__ int        sLast;

    const int t  = threadIdx.x;
    const int bi = blockIdx.x;
    const int g  = blockIdx.y;
    const int G  = gridDim.y;
    const int jbase = g * JTILE;

    // ---- load j tile (padding: x=0, sq=0, p=0 -> zero contribution) ----
    for (int k = t; k < JT2; k += THREADS) {
        int j0 = jbase + 2 * k, j1 = j0 + 1;
        float X0 = 0.f, Y0 = 0.f, Z0 = 0.f, P0 = 0.f, Q0 = 0.f, R0 = 0.f;
        float X1 = 0.f, Y1 = 0.f, Z1 = 0.f, P1 = 0.f, Q1 = 0.f, R1 = 0.f;
        if (j0 < N) {
            X0 = x[3 * j0] * SSCALE; Y0 = x[3 * j0 + 1] * SSCALE; Z0 = x[3 * j0 + 2] * SSCALE;
            P0 = clamp1(mom[3 * j0]); Q0 = clamp1(mom[3 * j0 + 1]); R0 = clamp1(mom[3 * j0 + 2]);
        }
        if (j1 < N) {
            X1 = x[3 * j1] * SSCALE; Y1 = x[3 * j1 + 1] * SSCALE; Z1 = x[3 * j1 + 2] * SSCALE;
            P1 = clamp1(mom[3 * j1]); Q1 = clamp1(mom[3 * j1 + 1]); R1 = clamp1(mom[3 * j1 + 2]);
        }
        float S0 = X0 * X0 + Y0 * Y0 + Z0 * Z0;
        float S1 = X1 * X1 + Y1 * Y1 + Z1 * Z1;
        ulonglong2 v;
        v.x = pk2(X0, X1); v.y = pk2(Y0, Y1); sT0[k] = v;
        v.x = pk2(Z0, Z1); v.y = pk2(S0, S1); sT1[k] = v;
        v.x = pk2(P0, P1); v.y = pk2(Q0, Q1); sT2[k] = v;
        sQz[k] = pk2(R0, R1);
    }
    __syncthreads();

    // ---- per-thread i state (broadcast packed) ----
    u64 n2x[IPT], n2y[IPT], n2z[IPT];   // packed (-2*xi_s)
    u64 sqi[IPT];                        // packed |xi_s|^2
    u64 pxi[IPT], pyi[IPT], pzi[IPT];   // packed clamped p_i
    u64 acx[IPT], acy[IPT], acz[IPT];   // sum e * p_j
    u64 awx[IPT], awy[IPT], awz[IPT];   // sum w * xj_s
    u64 aw [IPT];                        // sum w

    const int ibase = bi * ISPAN + t;
#pragma unroll
    for (int ii = 0; ii < IPT; ii++) {
        int i = ibase + ii * THREADS;
        float X = 0.f, Y = 0.f, Z = 0.f, P = 0.f, Q = 0.f, R = 0.f;
        if (i < N) {
            X = x[3 * i] * SSCALE; Y = x[3 * i + 1] * SSCALE; Z = x[3 * i + 2] * SSCALE;
            P = clamp1(mom[3 * i]); Q = clamp1(mom[3 * i + 1]); R = clamp1(mom[3 * i + 2]);
        }
        float S = X * X + Y * Y + Z * Z;
        n2x[ii] = pk2(-2.f * X, -2.f * X);
        n2y[ii] = pk2(-2.f * Y, -2.f * Y);
        n2z[ii] = pk2(-2.f * Z, -2.f * Z);
        sqi[ii] = pk2(S, S);
        pxi[ii] = pk2(P, P); pyi[ii] = pk2(Q, Q); pzi[ii] = pk2(R, R);
        acx[ii] = 0ull; acy[ii] = 0ull; acz[ii] = 0ull;
        awx[ii] = 0ull; awy[ii] = 0ull; awz[ii] = 0ull;
        aw [ii] = 0ull;
    }

    // packed constants
    const u64 MAG2  = pk2(MAGIC, MAGIC);
    const u64 NMAG2 = pk2(-MAGIC, -MAGIC);
    const u64 NONE2 = pk2(-1.0f, -1.0f);
    // 2^(-f), f in [-0.5,0.5]: deg-3 economized (deg4+deg5 Taylor terms folded),
    // max rel err ~1.1e-4 (output budget 1e-3)
    const u64 P3 = pk2(-0.05592090f, -0.05592090f);
    const u64 P2 = pk2( 0.24263160f,  0.24263160f);
    const u64 P1 = pk2(-0.69312100f, -0.69312100f);
    const u64 P0 = pk2( 0.99992486f,  0.99992486f);

    // ---- main pairwise loop: each iter = 2 j x IPT i ----
#pragma unroll 2
    for (int k = 0; k < JT2; k++) {
        ulonglong2 t0 = sT0[k], t1 = sT1[k], t2 = sT2[k];
        u64 xj = t0.x, yj = t0.y, zj = t1.x, sqj = t1.y;
        u64 qx = t2.x, qy = t2.y, qz = sQz[k];
#pragma unroll
        for (int ii = 0; ii < IPT; ii++) {
            u64 d2 = f2add(sqj, sqi[ii]);           // |xi|^2 + |xj|^2 (scaled)
            d2 = f2fma(n2x[ii], xj, d2);
            d2 = f2fma(n2y[ii], yj, d2);
            d2 = f2fma(n2z[ii], zj, d2);            // d2' = 72.13*|xi-xj|^2 (>= -eps)
            u64 fz = f2add(d2, MAG2);               // magic round: bits = 0x4B400000+n
            u64 nn = f2add(fz, NMAG2);              // n as float
            u64 ff = f2fma(nn, NONE2, d2);          // f = d2' - n in [-0.5, 0.5]
            u64 p  = f2fma(P3, ff, P2);             // 2^(-f), deg-3
            p = f2fma(p, ff, P1);
            p = f2fma(p, ff, P0);
            // scale 2^(-n): ALU only. min is the underflow clamp (n>=127 -> 0).
            float fz0, fz1; upk2(fz, fz0, fz1);
            unsigned b0 = min(__float_as_uint(fz0), 0x4B40007Fu);
            unsigned b1 = min(__float_as_uint(fz1), 0x4B40007Fu);
            float s0 = __uint_as_float(0x3F800000u - (b0 << 23));
            float s1 = __uint_as_float(0x3F800000u - (b1 << 23));
            u64 e = f2mul(p, pk2(s0, s1));          // K_ij = 2^(-d2')

            u64 pp = f2mul(pxi[ii], qx);
            pp = f2fma(pyi[ii], qy, pp);
            pp = f2fma(pzi[ii], qz, pp);            // p_i . p_j
            u64 w = f2mul(e, pp);                   // W_ij

            acx[ii] = f2fma(e, qx, acx[ii]);
            acy[ii] = f2fma(e, qy, acy[ii]);
            acz[ii] = f2fma(e, qz, acz[ii]);
            awx[ii] = f2fma(w, xj, awx[ii]);
            awy[ii] = f2fma(w, yj, awy[ii]);
            awz[ii] = f2fma(w, zj, awz[ii]);
            aw [ii] = f2add(aw[ii], w);
        }
    }

    // ---- write partials, coalesced [g][d][i] (one writer per slot) ----
#pragma unroll
    for (int ii = 0; ii < IPT; ii++) {
        int i = ibase + ii * THREADS;
        if (i < N) {
            float u, v;
            float* P = g_part[g];
            upk2(acx[ii], u, v); P[0 * MAXN + i] = u + v;
            upk2(acy[ii], u, v); P[1 * MAXN + i] = u + v;
            upk2(acz[ii], u, v); P[2 * MAXN + i] = u + v;
            upk2(awx[ii], u, v); P[3 * MAXN + i] = u + v;
            upk2(awy[ii], u, v); P[4 * MAXN + i] = u + v;
            upk2(awz[ii], u, v); P[5 * MAXN + i] = u + v;
            upk2(aw [ii], u, v); P[6 * MAXN + i] = u + v;
        }
    }

    // ---- fused cross-g reduction: last block of this i-column does it ----
    __threadfence();
    if (t == 0) {
        int old = atomicAdd(&g_cnt[bi], 1);
        sLast = (old == G - 1) ? 1 : 0;
    }
    __syncthreads();
    if (sLast) {
        const float DCA = -100.0f / SSCALE;   // for sum(w*xj_s): unscale + sign
#pragma unroll
        for (int ii = 0; ii < IPT; ii++) {
            int i = ibase + ii * THREADS;
            if (i < N) {
                float a0 = 0.f, a1 = 0.f, a2 = 0.f, a3 = 0.f, a4 = 0.f, a5 = 0.f, a6 = 0.f;
                for (int gg = 0; gg < G; gg++) {   // fixed order -> deterministic
                    const float* P = g_part[gg];
                    a0 += P[0 * MAXN + i]; a1 += P[1 * MAXN + i]; a2 += P[2 * MAXN + i];
                    a3 += P[3 * MAXN + i]; a4 += P[4 * MAXN + i]; a5 += P[5 * MAXN + i];
                    a6 += P[6 * MAXN + i];
                }
                // dcp
                out[3 * N + 3 * i + 0] = a0;
                out[3 * N + 3 * i + 1] = a1;
                out[3 * N + 3 * i + 2] = a2;
                // dmom = 100*( x_i * SumW - Sum(w x_j) )   (a3..a5 are scaled by s)
                out[3 * i + 0] = 100.0f * x[3 * i + 0] * a6 + DCA * a3;
                out[3 * i + 1] = 100.0f * x[3 * i + 1] * a6 + DCA * a4;
                out[3 * i + 2] = 100.0f * x[3 * i + 2] * a6 + DCA * a5;
            }
        }
        __syncthreads();
        if (t == 0) g_cnt[bi] = 0;   // self-reset for next (graph) replay
    }
}

extern "C" void kernel_launch(void* const* d_in, const int* in_sizes, int n_in,
                              void* d_out, int out_size)
{
    const float* mom = (const float*)d_in[0];
    const float* x   = (const float*)d_in[1];
    int N = in_sizes[0] / 3;
    if (N <= 0) return;
    if (N > MAXN) N = MAXN;  // scratch bound (problem uses N=8192)

    int G   = (N + JTILE - 1) / JTILE;
    int NBI = (N + ISPAN - 1) / ISPAN;
    dim3 grid(NBI, G);
    lddmm_main<<<grid, THREADS>>>(mom, x, (float*)d_out, N);
}

// round 13
// speedup vs baseline: 1.2551x; 1.2363x over previous
#include <cuda_runtime.h>
#include <cstdint>

// LDDMM variational shooting RHS, Gaussian kernel sigma=0.1, B=1, N=8192, D=3.
//
// dcp_i  = sum_j exp(-50*|xi-xj|^2) * p_j                    (p = clamp(mom,-1,1))
// dmom_i = 100 * ( x_i * sum_j W_ij  -  sum_j W_ij x_j ),  W_ij = K_ij (p_i.p_j)
//
// O(N^2) pairwise with fma.rn.f32x2 (2 j-points per instruction). Hot unit
// (2j x 1i) = 15 FMA2 + 2 MUFU:
//   d2n = 2 xi.xj - |xi|^2 - |xj|^2   (coords pre-scaled by s=sqrt(50 log2 e),
//                                      so d2n = -50 log2(e) |dx|^2)
//   K   = ex2.approx(d2n) per lane    (MUFU; underflow->0 is the clamp, and
//                                      MUFU cost = 16us chip-wide, hidden
//                                      under ~28us of FMA2 work)
//   accumulate {e*p_j, w*x_j, w}; dmom folded as x_i*SumW - Sum(w x_j).
// Cross-g reduction fused: last block per i-column (atomic counter) sums the
// per-g partials in fixed order (deterministic) and writes the output.

#define THREADS 128
#define IPT     2                 // i-points per thread
#define ISPAN   (THREADS * IPT)   // 256 i per block
#define JTILE   256               // j per block (1024 blocks -> wave balance)
#define JT2     (JTILE / 2)       // packed j-pairs in tile
#define MAXN    16384
#define MAXG    ((MAXN + JTILE - 1) / JTILE)
#define MAXBI   (MAXN / ISPAN)

// coordinate prescale: s^2 = 50*log2(e) = 72.13475204
#define SSCALE  8.4932180f

// partials: g_part[g][d*MAXN + i]; d=0..2: sum e*p_j ; d=3..5: sum w*x_j ; d=6: sum w
__device__ __align__(16) float g_part[MAXG][7 * MAXN];
__device__ int g_cnt[MAXBI];       // zero-init; self-resetting per launch

using u64 = unsigned long long;

__device__ __forceinline__ u64 pk2(float a, float b) {
    u64 r; asm("mov.b64 %0, {%1, %2};" : "=l"(r) : "f"(a), "f"(b)); return r;
}
__device__ __forceinline__ void upk2(u64 v, float& a, float& b) {
    asm("mov.b64 {%0, %1}, %2;" : "=f"(a), "=f"(b) : "l"(v));
}
__device__ __forceinline__ u64 f2add(u64 a, u64 b) {
    u64 r; asm("add.rn.f32x2 %0, %1, %2;" : "=l"(r) : "l"(a), "l"(b)); return r;
}
__device__ __forceinline__ u64 f2mul(u64 a, u64 b) {
    u64 r; asm("mul.rn.f32x2 %0, %1, %2;" : "=l"(r) : "l"(a), "l"(b)); return r;
}
__device__ __forceinline__ u64 f2fma(u64 a, u64 b, u64 c) {
    u64 r; asm("fma.rn.f32x2 %0, %1, %2, %3;" : "=l"(r) : "l"(a), "l"(b), "l"(c)); return r;
}
__device__ __forceinline__ float ex2a(float v) {
    float r; asm("ex2.approx.f32 %0, %1;" : "=f"(r) : "f"(v)); return r;
}

__device__ __forceinline__ float clamp1(float v) {
    return fminf(fmaxf(v, -1.0f), 1.0f);
}

__global__ __launch_bounds__(THREADS)
void lddmm_main(const float* __restrict__ mom, const float* __restrict__ x,
                float* __restrict__ out, int N)
{
    __shared__ ulonglong2 sT0[JT2];  // (xj, yj)    scaled coords, packed (j0,j1)
    __shared__ ulonglong2 sT1[JT2];  // (zj, nsqj)  nsqj = -|xj_s|^2
    __shared__ ulonglong2 sT2[JT2];  // (qx, qy)    clamped momenta
    __shared__ u64        sQz[JT2];  // qz
    __shared__ int        sLast;

    const int t  = threadIdx.x;
    const int bi = blockIdx.x;
    const int g  = blockIdx.y;
    const int G  = gridDim.y;
    const int jbase = g * JTILE;

    // ---- load j tile (padding: x=0, nsq=0, p=0 -> zero contribution) ----
    for (int k = t; k < JT2; k += THREADS) {
        int j0 = jbase + 2 * k, j1 = j0 + 1;
        float X0 = 0.f, Y0 = 0.f, Z0 = 0.f, P0 = 0.f, Q0 = 0.f, R0 = 0.f;
        float X1 = 0.f, Y1 = 0.f, Z1 = 0.f, P1 = 0.f, Q1 = 0.f, R1 = 0.f;
        if (j0 < N) {
            X0 = x[3 * j0] * SSCALE; Y0 = x[3 * j0 + 1] * SSCALE; Z0 = x[3 * j0 + 2] * SSCALE;
            P0 = clamp1(mom[3 * j0]); Q0 = clamp1(mom[3 * j0 + 1]); R0 = clamp1(mom[3 * j0 + 2]);
        }
        if (j1 < N) {
            X1 = x[3 * j1] * SSCALE; Y1 = x[3 * j1 + 1] * SSCALE; Z1 = x[3 * j1 + 2] * SSCALE;
            P1 = clamp1(mom[3 * j1]); Q1 = clamp1(mom[3 * j1 + 1]); R1 = clamp1(mom[3 * j1 + 2]);
        }
        float S0 = -(X0 * X0 + Y0 * Y0 + Z0 * Z0);
        float S1 = -(X1 * X1 + Y1 * Y1 + Z1 * Z1);
        ulonglong2 v;
        v.x = pk2(X0, X1); v.y = pk2(Y0, Y1); sT0[k] = v;
        v.x = pk2(Z0, Z1); v.y = pk2(S0, S1); sT1[k] = v;
        v.x = pk2(P0, P1); v.y = pk2(Q0, Q1); sT2[k] = v;
        sQz[k] = pk2(R0, R1);
    }
    __syncthreads();

    // ---- per-thread i state (broadcast packed) ----
    u64 p2x[IPT], p2y[IPT], p2z[IPT];   // packed (+2*xi_s)
    u64 nsqi[IPT];                       // packed -|xi_s|^2
    u64 pxi[IPT], pyi[IPT], pzi[IPT];   // packed clamped p_i
    u64 acx[IPT], acy[IPT], acz[IPT];   // sum e * p_j
    u64 awx[IPT], awy[IPT], awz[IPT];   // sum w * xj_s
    u64 aw [IPT];                        // sum w

    const int ibase = bi * ISPAN + t;
#pragma unroll
    for (int ii = 0; ii < IPT; ii++) {
        int i = ibase + ii * THREADS;
        float X = 0.f, Y = 0.f, Z = 0.f, P = 0.f, Q = 0.f, R = 0.f;
        if (i < N) {
            X = x[3 * i] * SSCALE; Y = x[3 * i + 1] * SSCALE; Z = x[3 * i + 2] * SSCALE;
            P = clamp1(mom[3 * i]); Q = clamp1(mom[3 * i + 1]); R = clamp1(mom[3 * i + 2]);
        }
        float S = -(X * X + Y * Y + Z * Z);
        p2x[ii] = pk2(2.f * X, 2.f * X);
        p2y[ii] = pk2(2.f * Y, 2.f * Y);
        p2z[ii] = pk2(2.f * Z, 2.f * Z);
        nsqi[ii] = pk2(S, S);
        pxi[ii] = pk2(P, P); pyi[ii] = pk2(Q, Q); pzi[ii] = pk2(R, R);
        acx[ii] = 0ull; acy[ii] = 0ull; acz[ii] = 0ull;
        awx[ii] = 0ull; awy[ii] = 0ull; awz[ii] = 0ull;
        aw [ii] = 0ull;
    }

    // ---- main pairwise loop: each iter = 2 j x IPT i ----
#pragma unroll 4
    for (int k = 0; k < JT2; k++) {
        ulonglong2 t0 = sT0[k], t1 = sT1[k], t2 = sT2[k];
        u64 xj = t0.x, yj = t0.y, zj = t1.x, nsqj = t1.y;
        u64 qx = t2.x, qy = t2.y, qz = sQz[k];
#pragma unroll
        for (int ii = 0; ii < IPT; ii++) {
            u64 d2n = f2add(nsqj, nsqi[ii]);        // -(|xi|^2 + |xj|^2)
            d2n = f2fma(p2x[ii], xj, d2n);
            d2n = f2fma(p2y[ii], yj, d2n);
            d2n = f2fma(p2z[ii], zj, d2n);          // = -50*log2(e)*|xi-xj|^2 <= 0
            float a, b; upk2(d2n, a, b);
            u64 e = pk2(ex2a(a), ex2a(b));          // K_ij = 2^(d2n)  (MUFU)

            u64 pp = f2mul(pxi[ii], qx);
            pp = f2fma(pyi[ii], qy, pp);
            pp = f2fma(pzi[ii], qz, pp);            // p_i . p_j
            u64 w = f2mul(e, pp);                   // W_ij

            acx[ii] = f2fma(e, qx, acx[ii]);
            acy[ii] = f2fma(e, qy, acy[ii]);
            acz[ii] = f2fma(e, qz, acz[ii]);
            awx[ii] = f2fma(w, xj, awx[ii]);
            awy[ii] = f2fma(w, yj, awy[ii]);
            awz[ii] = f2fma(w, zj, awz[ii]);
            aw [ii] = f2add(aw[ii], w);
        }
    }

    // ---- write partials, coalesced [g][d][i] (one writer per slot) ----
#pragma unroll
    for (int ii = 0; ii < IPT; ii++) {
        int i = ibase + ii * THREADS;
        if (i < N) {
            float u, v;
            float* P = g_part[g];
            upk2(acx[ii], u, v); P[0 * MAXN + i] = u + v;
            upk2(acy[ii], u, v); P[1 * MAXN + i] = u + v;
            upk2(acz[ii], u, v); P[2 * MAXN + i] = u + v;
            upk2(awx[ii], u, v); P[3 * MAXN + i] = u + v;
            upk2(awy[ii], u, v); P[4 * MAXN + i] = u + v;
            upk2(awz[ii], u, v); P[5 * MAXN + i] = u + v;
            upk2(aw [ii], u, v); P[6 * MAXN + i] = u + v;
        }
    }

    // ---- fused cross-g reduction: last block of this i-column does it ----
    __threadfence();
    if (t == 0) {
        int old = atomicAdd(&g_cnt[bi], 1);
        sLast = (old == G - 1) ? 1 : 0;
    }
    __syncthreads();
    if (sLast) {
        const float DCA = -100.0f / SSCALE;   // for sum(w*xj_s): unscale + sign
#pragma unroll
        for (int ii = 0; ii < IPT; ii++) {
            int i = ibase + ii * THREADS;
            if (i < N) {
                float a0 = 0.f, a1 = 0.f, a2 = 0.f, a3 = 0.f, a4 = 0.f, a5 = 0.f, a6 = 0.f;
                for (int gg = 0; gg < G; gg++) {   // fixed order -> deterministic
                    const float* P = g_part[gg];
                    a0 += P[0 * MAXN + i]; a1 += P[1 * MAXN + i]; a2 += P[2 * MAXN + i];
                    a3 += P[3 * MAXN + i]; a4 += P[4 * MAXN + i]; a5 += P[5 * MAXN + i];
                    a6 += P[6 * MAXN + i];
                }
                // dcp
                out[3 * N + 3 * i + 0] = a0;
                out[3 * N + 3 * i + 1] = a1;
                out[3 * N + 3 * i + 2] = a2;
                // dmom = 100*( x_i * SumW - Sum(w x_j) )   (a3..a5 carry scale s)
                out[3 * i + 0] = 100.0f * x[3 * i + 0] * a6 + DCA * a3;
                out[3 * i + 1] = 100.0f * x[3 * i + 1] * a6 + DCA * a4;
                out[3 * i + 2] = 100.0f * x[3 * i + 2] * a6 + DCA * a5;
            }
        }
        __syncthreads();
        if (t == 0) g_cnt[bi] = 0;   // self-reset for next (graph) replay
    }
}

extern "C" void kernel_launch(void* const* d_in, const int* in_sizes, int n_in,
                              void* d_out, int out_size)
{
    const float* mom = (const float*)d_in[0];
    const float* x   = (const float*)d_in[1];
    int N = in_sizes[0] / 3;
    if (N <= 0) return;
    if (N > MAXN) N = MAXN;  // scratch bound (problem uses N=8192)

    int G   = (N + JTILE - 1) / JTILE;
    int NBI = (N + ISPAN - 1) / ISPAN;
    dim3 grid(NBI, G);
    lddmm_main<<<grid, THREADS>>>(mom, x, (float*)d_out, N);
}

// round 14
// speedup vs baseline: 1.3035x; 1.0385x over previous
#include <cuda_runtime.h>
#include <cstdint>

// LDDMM variational shooting RHS, Gaussian kernel sigma=0.1, B=1, N=8192, D=3.
//
// dcp_i  = sum_j exp(-50*|xi-xj|^2) * p_j                    (p = clamp(mom,-1,1))
// dmom_i = 100 * ( x_i * sum_j W_ij  -  sum_j W_ij x_j ),  W_ij = K_ij (p_i.p_j)
//
// O(N^2) pairwise with fma.rn.f32x2 (2 j-points per instruction). Hot unit
// (2j x 1i) = 15 FMA2 + 2 MUFU. IPT=1 (vs 2 before): same total FMA2 work, but
// per-thread register state halves (~72 -> ~48 regs), doubling resident warps
// (launch_bounds(128,8) -> 50% occ) to cover the d2n->ex2->w dependency chain
// that previously exposed ~46% of the runtime as latency.
//   d2n = 2 xi.xj - |xi|^2 - |xj|^2  (coords pre-scaled by s=sqrt(50 log2 e))
//   K   = ex2.approx(d2n) per lane   (MUFU, underflow->0 = free clamp)
//   accumulate {e*p_j, w*x_j, w}; dmom folded as x_i*SumW - Sum(w x_j).
// Cross-g reduction fused: last block per i-column (atomic counter) sums the
// per-g partials in fixed order (deterministic) and writes the output.

#define THREADS 128
#define ISPAN   THREADS           // 128 i per block (IPT=1)
#define JTILE   256               // j per block
#define JT2     (JTILE / 2)       // packed j-pairs in tile
#define MAXN    16384
#define MAXG    ((MAXN + JTILE - 1) / JTILE)
#define MAXBI   (MAXN / ISPAN)

// coordinate prescale: s^2 = 50*log2(e) = 72.13475204
#define SSCALE  8.4932180f

// partials: g_part[g][d*MAXN + i]; d=0..2: sum e*p_j ; d=3..5: sum w*x_j ; d=6: sum w
__device__ __align__(16) float g_part[MAXG][7 * MAXN];
__device__ int g_cnt[MAXBI];       // zero-init; self-resetting per launch

using u64 = unsigned long long;

__device__ __forceinline__ u64 pk2(float a, float b) {
    u64 r; asm("mov.b64 %0, {%1, %2};" : "=l"(r) : "f"(a), "f"(b)); return r;
}
__device__ __forceinline__ void upk2(u64 v, float& a, float& b) {
    asm("mov.b64 {%0, %1}, %2;" : "=f"(a), "=f"(b) : "l"(v));
}
__device__ __forceinline__ u64 f2add(u64 a, u64 b) {
    u64 r; asm("add.rn.f32x2 %0, %1, %2;" : "=l"(r) : "l"(a), "l"(b)); return r;
}
__device__ __forceinline__ u64 f2mul(u64 a, u64 b) {
    u64 r; asm("mul.rn.f32x2 %0, %1, %2;" : "=l"(r) : "l"(a), "l"(b)); return r;
}
__device__ __forceinline__ u64 f2fma(u64 a, u64 b, u64 c) {
    u64 r; asm("fma.rn.f32x2 %0, %1, %2, %3;" : "=l"(r) : "l"(a), "l"(b), "l"(c)); return r;
}
__device__ __forceinline__ float ex2a(float v) {
    float r; asm("ex2.approx.f32 %0, %1;" : "=f"(r) : "f"(v)); return r;
}

__device__ __forceinline__ float clamp1(float v) {
    return fminf(fmaxf(v, -1.0f), 1.0f);
}

__global__ __launch_bounds__(THREADS, 8)
void lddmm_main(const float* __restrict__ mom, const float* __restrict__ x,
                float* __restrict__ out, int N)
{
    __shared__ ulonglong2 sT0[JT2];  // (xj, yj)    scaled coords, packed (j0,j1)
    __shared__ ulonglong2 sT1[JT2];  // (zj, nsqj)  nsqj = -|xj_s|^2
    __shared__ ulonglong2 sT2[JT2];  // (qx, qy)    clamped momenta
    __shared__ u64        sQz[JT2];  // qz
    __shared__ int        sLast;

    const int t  = threadIdx.x;
    const int bi = blockIdx.x;
    const int g  = blockIdx.y;
    const int G  = gridDim.y;
    const int jbase = g * JTILE;

    // ---- load j tile (padding: x=0, nsq=0, p=0 -> zero contribution) ----
    for (int k = t; k < JT2; k += THREADS) {
        int j0 = jbase + 2 * k, j1 = j0 + 1;
        float X0 = 0.f, Y0 = 0.f, Z0 = 0.f, P0 = 0.f, Q0 = 0.f, R0 = 0.f;
        float X1 = 0.f, Y1 = 0.f, Z1 = 0.f, P1 = 0.f, Q1 = 0.f, R1 = 0.f;
        if (j0 < N) {
            X0 = x[3 * j0] * SSCALE; Y0 = x[3 * j0 + 1] * SSCALE; Z0 = x[3 * j0 + 2] * SSCALE;
            P0 = clamp1(mom[3 * j0]); Q0 = clamp1(mom[3 * j0 + 1]); R0 = clamp1(mom[3 * j0 + 2]);
        }
        if (j1 < N) {
            X1 = x[3 * j1] * SSCALE; Y1 = x[3 * j1 + 1] * SSCALE; Z1 = x[3 * j1 + 2] * SSCALE;
            P1 = clamp1(mom[3 * j1]); Q1 = clamp1(mom[3 * j1 + 1]); R1 = clamp1(mom[3 * j1 + 2]);
        }
        float S0 = -(X0 * X0 + Y0 * Y0 + Z0 * Z0);
        float S1 = -(X1 * X1 + Y1 * Y1 + Z1 * Z1);
        ulonglong2 v;
        v.x = pk2(X0, X1); v.y = pk2(Y0, Y1); sT0[k] = v;
        v.x = pk2(Z0, Z1); v.y = pk2(S0, S1); sT1[k] = v;
        v.x = pk2(P0, P1); v.y = pk2(Q0, Q1); sT2[k] = v;
        sQz[k] = pk2(R0, R1);
    }
    __syncthreads();

    // ---- per-thread i state (broadcast packed), one i per thread ----
    const int i = bi * ISPAN + t;
    float X = 0.f, Y = 0.f, Z = 0.f, P = 0.f, Q = 0.f, R = 0.f;
    if (i < N) {
        X = x[3 * i] * SSCALE; Y = x[3 * i + 1] * SSCALE; Z = x[3 * i + 2] * SSCALE;
        P = clamp1(mom[3 * i]); Q = clamp1(mom[3 * i + 1]); R = clamp1(mom[3 * i + 2]);
    }
    const float S = -(X * X + Y * Y + Z * Z);
    const u64 p2x = pk2(2.f * X, 2.f * X);
    const u64 p2y = pk2(2.f * Y, 2.f * Y);
    const u64 p2z = pk2(2.f * Z, 2.f * Z);
    const u64 nsqi = pk2(S, S);
    const u64 pxi = pk2(P, P), pyi = pk2(Q, Q), pzi = pk2(R, R);

    u64 acx = 0ull, acy = 0ull, acz = 0ull;   // sum e * p_j
    u64 awx = 0ull, awy = 0ull, awz = 0ull;   // sum w * xj_s
    u64 aw  = 0ull;                            // sum w

    // ---- main pairwise loop: each iter = 2 j x 1 i; unroll 8 -> 8 indep units ----
#pragma unroll 8
    for (int k = 0; k < JT2; k++) {
        ulonglong2 t0 = sT0[k], t1 = sT1[k], t2 = sT2[k];
        u64 xj = t0.x, yj = t0.y, zj = t1.x, nsqj = t1.y;
        u64 qx = t2.x, qy = t2.y, qz = sQz[k];

        u64 d2n = f2add(nsqj, nsqi);            // -(|xi|^2 + |xj|^2)
        d2n = f2fma(p2x, xj, d2n);
        d2n = f2fma(p2y, yj, d2n);
        d2n = f2fma(p2z, zj, d2n);              // = -50*log2(e)*|xi-xj|^2 <= 0
        float a, b; upk2(d2n, a, b);
        u64 e = pk2(ex2a(a), ex2a(b));          // K_ij = 2^(d2n)  (MUFU)

        u64 pp = f2mul(pxi, qx);
        pp = f2fma(pyi, qy, pp);
        pp = f2fma(pzi, qz, pp);                // p_i . p_j
        u64 w = f2mul(e, pp);                   // W_ij

        acx = f2fma(e, qx, acx);
        acy = f2fma(e, qy, acy);
        acz = f2fma(e, qz, acz);
        awx = f2fma(w, xj, awx);
        awy = f2fma(w, yj, awy);
        awz = f2fma(w, zj, awz);
        aw  = f2add(aw, w);
    }

    // ---- write partials, coalesced [g][d][i] (one writer per slot) ----
    if (i < N) {
        float u, v;
        float* Pp = g_part[g];
        upk2(acx, u, v); Pp[0 * MAXN + i] = u + v;
        upk2(acy, u, v); Pp[1 * MAXN + i] = u + v;
        upk2(acz, u, v); Pp[2 * MAXN + i] = u + v;
        upk2(awx, u, v); Pp[3 * MAXN + i] = u + v;
        upk2(awy, u, v); Pp[4 * MAXN + i] = u + v;
        upk2(awz, u, v); Pp[5 * MAXN + i] = u + v;
        upk2(aw , u, v); Pp[6 * MAXN + i] = u + v;
    }

    // ---- fused cross-g reduction: last block of this i-column does it ----
    __threadfence();
    if (t == 0) {
        int old = atomicAdd(&g_cnt[bi], 1);
        sLast = (old == G - 1) ? 1 : 0;
    }
    __syncthreads();
    if (sLast) {
        const float DCA = -100.0f / SSCALE;   // for sum(w*xj_s): unscale + sign
        if (i < N) {
            float a0 = 0.f, a1 = 0.f, a2 = 0.f, a3 = 0.f, a4 = 0.f, a5 = 0.f, a6 = 0.f;
            for (int gg = 0; gg < G; gg++) {   // fixed order -> deterministic
                const float* Pp = g_part[gg];
                a0 += Pp[0 * MAXN + i]; a1 += Pp[1 * MAXN + i]; a2 += Pp[2 * MAXN + i];
                a3 += Pp[3 * MAXN + i]; a4 += Pp[4 * MAXN + i]; a5 += Pp[5 * MAXN + i];
                a6 += Pp[6 * MAXN + i];
            }
            // dcp
            out[3 * N + 3 * i + 0] = a0;
            out[3 * N + 3 * i + 1] = a1;
            out[3 * N + 3 * i + 2] = a2;
            // dmom = 100*( x_i * SumW - Sum(w x_j) )   (a3..a5 carry scale s)
            out[3 * i + 0] = 100.0f * x[3 * i + 0] * a6 + DCA * a3;
            out[3 * i + 1] = 100.0f * x[3 * i + 1] * a6 + DCA * a4;
            out[3 * i + 2] = 100.0f * x[3 * i + 2] * a6 + DCA * a5;
        }
        __syncthreads();
        if (t == 0) g_cnt[bi] = 0;   // self-reset for next (graph) replay
    }
}

extern "C" void kernel_launch(void* const* d_in, const int* in_sizes, int n_in,
                              void* d_out, int out_size)
{
    const float* mom = (const float*)d_in[0];
    const float* x   = (const float*)d_in[1];
    int N = in_sizes[0] / 3;
    if (N <= 0) return;
    if (N > MAXN) N = MAXN;  // scratch bound (problem uses N=8192)

    int G   = (N + JTILE - 1) / JTILE;
    int NBI = (N + ISPAN - 1) / ISPAN;
    dim3 grid(NBI, G);
    lddmm_main<<<grid, THREADS>>>(mom, x, (float*)d_out, N);
}

// round 15
// speedup vs baseline: 1.3608x; 1.0439x over previous
#include <cuda_runtime.h>
#include <cstdint>

// LDDMM variational shooting RHS, Gaussian kernel sigma=0.1, B=1, N=8192, D=3.
//
// dcp_i  = sum_j exp(-50*|xi-xj|^2) * p_j                    (p = clamp(mom,-1,1))
// dmom_i = 100 * ( x_i * sum_j W_ij  -  sum_j W_ij x_j ),  W_ij = K_ij (p_i.p_j)
//
// O(N^2) pairwise with fma.rn.f32x2 (2 j-points per instruction). Hot unit
// (2j x 1i) = 15 FMA2 + 2 MUFU, IPT=1, regs=64 -> 8 blocks/SM.
// THIS ROUND: JTILE 256 -> 512 so grid = 64 x 16 = 1024 blocks <= 1184
// resident slots (148 SM x 8): a SINGLE wave, no wave quantization, and the
// per-block prologue/epilogue share halves.
//   d2n = 2 xi.xj - |xi|^2 - |xj|^2  (coords pre-scaled by s=sqrt(50 log2 e))
//   K   = ex2.approx(d2n) per lane   (MUFU, underflow->0 = free clamp)
//   accumulate {e*p_j, w*x_j, w}; dmom folded as x_i*SumW - Sum(w x_j).
// Cross-g reduction fused: last block per i-column (atomic counter) sums the
// per-g partials in fixed order (deterministic) and writes the output.

#define THREADS 128
#define ISPAN   THREADS           // 128 i per block (IPT=1)
#define JTILE   512               // j per block -> 1024 blocks total = one wave
#define JT2     (JTILE / 2)       // packed j-pairs in tile
#define MAXN    16384
#define MAXG    ((MAXN + JTILE - 1) / JTILE)
#define MAXBI   (MAXN / ISPAN)

// coordinate prescale: s^2 = 50*log2(e) = 72.13475204
#define SSCALE  8.4932180f

// partials: g_part[g][d*MAXN + i]; d=0..2: sum e*p_j ; d=3..5: sum w*x_j ; d=6: sum w
__device__ __align__(16) float g_part[MAXG][7 * MAXN];
__device__ int g_cnt[MAXBI];       // zero-init; self-resetting per launch

using u64 = unsigned long long;

__device__ __forceinline__ u64 pk2(float a, float b) {
    u64 r; asm("mov.b64 %0, {%1, %2};" : "=l"(r) : "f"(a), "f"(b)); return r;
}
__device__ __forceinline__ void upk2(u64 v, float& a, float& b) {
    asm("mov.b64 {%0, %1}, %2;" : "=f"(a), "=f"(b) : "l"(v));
}
__device__ __forceinline__ u64 f2add(u64 a, u64 b) {
    u64 r; asm("add.rn.f32x2 %0, %1, %2;" : "=l"(r) : "l"(a), "l"(b)); return r;
}
__device__ __forceinline__ u64 f2mul(u64 a, u64 b) {
    u64 r; asm("mul.rn.f32x2 %0, %1, %2;" : "=l"(r) : "l"(a), "l"(b)); return r;
}
__device__ __forceinline__ u64 f2fma(u64 a, u64 b, u64 c) {
    u64 r; asm("fma.rn.f32x2 %0, %1, %2, %3;" : "=l"(r) : "l"(a), "l"(b), "l"(c)); return r;
}
__device__ __forceinline__ float ex2a(float v) {
    float r; asm("ex2.approx.f32 %0, %1;" : "=f"(r) : "f"(v)); return r;
}

__device__ __forceinline__ float clamp1(float v) {
    return fminf(fmaxf(v, -1.0f), 1.0f);
}

__global__ __launch_bounds__(THREADS, 8)
void lddmm_main(const float* __restrict__ mom, const float* __restrict__ x,
                float* __restrict__ out, int N)
{
    __shared__ ulonglong2 sT0[JT2];  // (xj, yj)    scaled coords, packed (j0,j1)
    __shared__ ulonglong2 sT1[JT2];  // (zj, nsqj)  nsqj = -|xj_s|^2
    __shared__ ulonglong2 sT2[JT2];  // (qx, qy)    clamped momenta
    __shared__ u64        sQz[JT2];  // qz
    __shared__ int        sLast;

    const int t  = threadIdx.x;
    const int bi = blockIdx.x;
    const int g  = blockIdx.y;
    const int G  = gridDim.y;
    const int jbase = g * JTILE;

    // ---- load j tile (padding: x=0, nsq=0, p=0 -> zero contribution) ----
    for (int k = t; k < JT2; k += THREADS) {
        int j0 = jbase + 2 * k, j1 = j0 + 1;
        float X0 = 0.f, Y0 = 0.f, Z0 = 0.f, P0 = 0.f, Q0 = 0.f, R0 = 0.f;
        float X1 = 0.f, Y1 = 0.f, Z1 = 0.f, P1 = 0.f, Q1 = 0.f, R1 = 0.f;
        if (j0 < N) {
            X0 = x[3 * j0] * SSCALE; Y0 = x[3 * j0 + 1] * SSCALE; Z0 = x[3 * j0 + 2] * SSCALE;
            P0 = clamp1(mom[3 * j0]); Q0 = clamp1(mom[3 * j0 + 1]); R0 = clamp1(mom[3 * j0 + 2]);
        }
        if (j1 < N) {
            X1 = x[3 * j1] * SSCALE; Y1 = x[3 * j1 + 1] * SSCALE; Z1 = x[3 * j1 + 2] * SSCALE;
            P1 = clamp1(mom[3 * j1]); Q1 = clamp1(mom[3 * j1 + 1]); R1 = clamp1(mom[3 * j1 + 2]);
        }
        float S0 = -(X0 * X0 + Y0 * Y0 + Z0 * Z0);
        float S1 = -(X1 * X1 + Y1 * Y1 + Z1 * Z1);
        ulonglong2 v;
        v.x = pk2(X0, X1); v.y = pk2(Y0, Y1); sT0[k] = v;
        v.x = pk2(Z0, Z1); v.y = pk2(S0, S1); sT1[k] = v;
        v.x = pk2(P0, P1); v.y = pk2(Q0, Q1); sT2[k] = v;
        sQz[k] = pk2(R0, R1);
    }
    __syncthreads();

    // ---- per-thread i state (broadcast packed), one i per thread ----
    const int i = bi * ISPAN + t;
    float X = 0.f, Y = 0.f, Z = 0.f, P = 0.f, Q = 0.f, R = 0.f;
    if (i < N) {
        X = x[3 * i] * SSCALE; Y = x[3 * i + 1] * SSCALE; Z = x[3 * i + 2] * SSCALE;
        P = clamp1(mom[3 * i]); Q = clamp1(mom[3 * i + 1]); R = clamp1(mom[3 * i + 2]);
    }
    const float S = -(X * X + Y * Y + Z * Z);
    const u64 p2x = pk2(2.f * X, 2.f * X);
    const u64 p2y = pk2(2.f * Y, 2.f * Y);
    const u64 p2z = pk2(2.f * Z, 2.f * Z);
    const u64 nsqi = pk2(S, S);
    const u64 pxi = pk2(P, P), pyi = pk2(Q, Q), pzi = pk2(R, R);

    u64 acx = 0ull, acy = 0ull, acz = 0ull;   // sum e * p_j
    u64 awx = 0ull, awy = 0ull, awz = 0ull;   // sum w * xj_s
    u64 aw  = 0ull;                            // sum w

    // ---- main pairwise loop: each iter = 2 j x 1 i; unroll 8 -> 8 indep units ----
#pragma unroll 8
    for (int k = 0; k < JT2; k++) {
        ulonglong2 t0 = sT0[k], t1 = sT1[k], t2 = sT2[k];
        u64 xj = t0.x, yj = t0.y, zj = t1.x, nsqj = t1.y;
        u64 qx = t2.x, qy = t2.y, qz = sQz[k];

        u64 d2n = f2add(nsqj, nsqi);            // -(|xi|^2 + |xj|^2)
        d2n = f2fma(p2x, xj, d2n);
        d2n = f2fma(p2y, yj, d2n);
        d2n = f2fma(p2z, zj, d2n);              // = -50*log2(e)*|xi-xj|^2 <= 0
        float a, b; upk2(d2n, a, b);
        u64 e = pk2(ex2a(a), ex2a(b));          // K_ij = 2^(d2n)  (MUFU)

        u64 pp = f2mul(pxi, qx);
        pp = f2fma(pyi, qy, pp);
        pp = f2fma(pzi, qz, pp);                // p_i . p_j
        u64 w = f2mul(e, pp);                   // W_ij

        acx = f2fma(e, qx, acx);
        acy = f2fma(e, qy, acy);
        acz = f2fma(e, qz, acz);
        awx = f2fma(w, xj, awx);
        awy = f2fma(w, yj, awy);
        awz = f2fma(w, zj, awz);
        aw  = f2add(aw, w);
    }

    // ---- write partials, coalesced [g][d][i] (one writer per slot) ----
    if (i < N) {
        float u, v;
        float* Pp = g_part[g];
        upk2(acx, u, v); Pp[0 * MAXN + i] = u + v;
        upk2(acy, u, v); Pp[1 * MAXN + i] = u + v;
        upk2(acz, u, v); Pp[2 * MAXN + i] = u + v;
        upk2(awx, u, v); Pp[3 * MAXN + i] = u + v;
        upk2(awy, u, v); Pp[4 * MAXN + i] = u + v;
        upk2(awz, u, v); Pp[5 * MAXN + i] = u + v;
        upk2(aw , u, v); Pp[6 * MAXN + i] = u + v;
    }

    // ---- fused cross-g reduction: last block of this i-column does it ----
    __threadfence();
    if (t == 0) {
        int old = atomicAdd(&g_cnt[bi], 1);
        sLast = (old == G - 1) ? 1 : 0;
    }
    __syncthreads();
    if (sLast) {
        const float DCA = -100.0f / SSCALE;   // for sum(w*xj_s): unscale + sign
        if (i < N) {
            float a0 = 0.f, a1 = 0.f, a2 = 0.f, a3 = 0.f, a4 = 0.f, a5 = 0.f, a6 = 0.f;
            for (int gg = 0; gg < G; gg++) {   // fixed order -> deterministic
                const float* Pp = g_part[gg];
                a0 += Pp[0 * MAXN + i]; a1 += Pp[1 * MAXN + i]; a2 += Pp[2 * MAXN + i];
                a3 += Pp[3 * MAXN + i]; a4 += Pp[4 * MAXN + i]; a5 += Pp[5 * MAXN + i];
                a6 += Pp[6 * MAXN + i];
            }
            // dcp
            out[3 * N + 3 * i + 0] = a0;
            out[3 * N + 3 * i + 1] = a1;
            out[3 * N + 3 * i + 2] = a2;
            // dmom = 100*( x_i * SumW - Sum(w x_j) )   (a3..a5 carry scale s)
            out[3 * i + 0] = 100.0f * x[3 * i + 0] * a6 + DCA * a3;
            out[3 * i + 1] = 100.0f * x[3 * i + 1] * a6 + DCA * a4;
            out[3 * i + 2] = 100.0f * x[3 * i + 2] * a6 + DCA * a5;
        }
        __syncthreads();
        if (t == 0) g_cnt[bi] = 0;   // self-reset for next (graph) replay
    }
}

extern "C" void kernel_launch(void* const* d_in, const int* in_sizes, int n_in,
                              void* d_out, int out_size)
{
    const float* mom = (const float*)d_in[0];
    const float* x   = (const float*)d_in[1];
    int N = in_sizes[0] / 3;
    if (N <= 0) return;
    if (N > MAXN) N = MAXN;  // scratch bound (problem uses N=8192)

    int G   = (N + JTILE - 1) / JTILE;
    int NBI = (N + ISPAN - 1) / ISPAN;
    dim3 grid(NBI, G);
    lddmm_main<<<grid, THREADS>>>(mom, x, (float*)d_out, N);
}